// round 3
// baseline (speedup 1.0000x reference)
#include <cuda_runtime.h>
#include <cuda_bf16.h>

#define BSZ       64
#define SEQLEN    512
#define NT        48
#define NT2       (NT * NT)
#define START_TAG 46
#define END_TAG   47
#define TPB       384   // 48 columns x 8 lanes

// Runtime-detected target dtype flag (1 = int64, 0 = int32).
__device__ int g_is64;

// Prep kernel: zero the output scalar and detect target dtype.
// If target is int64 (values 0..45), every odd int32 word is 0.
// For int32 data the odd words are random tags in [0,46) -> all-zero
// probability ~ (1/46)^32 ~ 0.
__global__ void crf_prep(const int* __restrict__ tgt32, float* __restrict__ out) {
    int lane = threadIdx.x;
    int v = tgt32[2 * lane + 1];
    int all0 = __all_sync(0xffffffffu, v == 0);
    if (lane == 0) {
        g_is64 = all0;
        out[0] = 0.0f;
    }
}

// One CTA per batch. 48 columns (j), 8 lanes per column reducing over i.
// Per step t:
//   raw[j] = log( sum_i exp( r[i] - m + tr[t][i][j] ) ),  m = r[0]
//   r <- raw,  C += m          (true forward value = r + C)
// The per-column max of the reference is replaced by the scalar offset m,
// which keeps exp arguments bounded (values are logsumexps of the same
// distribution; spread is a few units). EPS=1e-12 is negligible since the
// sum always contains a term >= exp(-spread).
__global__ __launch_bounds__(TPB, 1) void crf_main(
    const float* __restrict__ tr,
    const void*  __restrict__ tgt,
    float*       __restrict__ out)
{
    __shared__ float shr[2][NT];
    __shared__ float ts_sh;

    const int tid = threadIdx.x;
    const int b   = blockIdx.x;
    const int j   = tid >> 3;   // column 0..47
    const int sub = tid & 7;    // reduction lane 0..7

    const float* __restrict__ tb = tr + (size_t)b * SEQLEN * NT2;

    if (tid == 0) ts_sh = 0.0f;
    // r_1 = transition[b, 0, START, :]
    if (tid < NT) shr[0][tid] = tb[START_TAG * NT + tid];

    // ---- target path score (gathered) ----
    const int is64 = g_is64;
    float ts = 0.0f;
    for (int s = tid; s < SEQLEN; s += TPB) {
        int cur, prv;
        if (is64) {
            const long long* t64 = (const long long*)tgt + (size_t)b * SEQLEN;
            cur = (int)t64[s];
            prv = (s == 0) ? START_TAG : (int)t64[s - 1];
        } else {
            const int* t32 = (const int*)tgt + b * SEQLEN;
            cur = t32[s];
            prv = (s == 0) ? START_TAG : t32[s - 1];
        }
        ts += tb[(size_t)s * NT2 + prv * NT + cur];
    }
    #pragma unroll
    for (int m = 16; m; m >>= 1) ts += __shfl_xor_sync(0xffffffffu, ts, m);
    if ((tid & 31) == 0) atomicAdd(&ts_sh, ts);

    // ---- forward recurrence with distance-2 register prefetch ----
    const int o0 = sub * NT + j;
    const int o1 = o0 +  8 * NT;
    const int o2 = o0 + 16 * NT;
    const int o3 = o0 + 24 * NT;
    const int o4 = o0 + 32 * NT;
    const int o5 = o0 + 40 * NT;

    float b0[6], b1[6], b2[6];
    {
        const float* p1 = tb + (size_t)1 * NT2;
        b1[0] = p1[o0]; b1[1] = p1[o1]; b1[2] = p1[o2];
        b1[3] = p1[o3]; b1[4] = p1[o4]; b1[5] = p1[o5];
        const float* p2 = tb + (size_t)2 * NT2;
        b2[0] = p2[o0]; b2[1] = p2[o1]; b2[2] = p2[o2];
        b2[3] = p2[o3]; b2[4] = p2[o4]; b2[5] = p2[o5];
    }
    float C = 0.0f;

#define STEP(T, CB, NB)                                                       \
    do {                                                                      \
        if ((T) + 2 < SEQLEN) {                                               \
            const float* pp = tb + (size_t)((T) + 2) * NT2;                   \
            NB[0] = pp[o0]; NB[1] = pp[o1]; NB[2] = pp[o2];                   \
            NB[3] = pp[o3]; NB[4] = pp[o4]; NB[5] = pp[o5];                   \
        }                                                                     \
        __syncthreads();                                                      \
        {                                                                     \
            const float* rin = shr[((T) + 1) & 1];                            \
            float m = rin[0];                                                 \
            C += m;                                                           \
            float e0 = __expf(rin[sub     ] - m + CB[0]);                     \
            float e1 = __expf(rin[sub +  8] - m + CB[1]);                     \
            float e2 = __expf(rin[sub + 16] - m + CB[2]);                     \
            float e3 = __expf(rin[sub + 24] - m + CB[3]);                     \
            float e4 = __expf(rin[sub + 32] - m + CB[4]);                     \
            float e5 = __expf(rin[sub + 40] - m + CB[5]);                     \
            float s = ((e0 + e1) + (e2 + e3)) + (e4 + e5);                    \
            s += __shfl_xor_sync(0xffffffffu, s, 1);                          \
            s += __shfl_xor_sync(0xffffffffu, s, 2);                          \
            s += __shfl_xor_sync(0xffffffffu, s, 4);                          \
            if (sub == 0) shr[(T) & 1][j] = __logf(s);                        \
        }                                                                     \
    } while (0)

    // 511 steps total: 170 x 3 unrolled + 1 tail. Buffer rotation:
    // step t consumes buf[t%3] and prefetches t+2 into buf[(t+2)%3].
    for (int it = 0; it < 170; ++it) {
        int t = 1 + it * 3;
        STEP(t,     b1, b0);
        STEP(t + 1, b2, b1);
        STEP(t + 2, b0, b2);
    }
    STEP(511, b1, b0);
#undef STEP

    __syncthreads();
    if (tid == 0) {
        float F = shr[1][END_TAG] + C;  // true forw[b, END]
        atomicAdd(out, (F - ts_sh) * (1.0f / (float)BSZ));
    }
}

extern "C" void kernel_launch(void* const* d_in, const int* in_sizes, int n_in,
                              void* d_out, int out_size) {
    const void* trans = d_in[0];
    const void* tgt   = d_in[1];
    // Defensive: identify tensors by size (transition is 75.5M elems, target 32K).
    if (n_in >= 2 && in_sizes[0] < in_sizes[1]) {
        trans = d_in[1];
        tgt   = d_in[0];
    }
    crf_prep<<<1, 32>>>((const int*)tgt, (float*)d_out);
    crf_main<<<BSZ, TPB>>>((const float*)trans, tgt, (float*)d_out);
}

// round 4
// speedup vs baseline: 1.0160x; 1.0160x over previous
#include <cuda_runtime.h>
#include <cuda_bf16.h>

#define BSZ       64
#define SEQLEN    512
#define NT        48
#define NT2       (NT * NT)
#define START_TAG 46
#define END_TAG   47
#define TPB       384   // 48 columns x 8 lanes

// Runtime-detected target dtype flag (1 = int64, 0 = int32).
__device__ int g_is64;

// Prep kernel: zero the output scalar and detect target dtype.
// If target is int64 (values 0..45), every odd int32 word is 0.
// For int32 data the odd words are random tags in [0,46) -> all-zero
// probability ~ (1/46)^32 ~ 0.
__global__ void crf_prep(const int* __restrict__ tgt32, float* __restrict__ out) {
    int lane = threadIdx.x;
    int v = tgt32[2 * lane + 1];
    int all0 = __all_sync(0xffffffffu, v == 0);
    if (lane == 0) {
        g_is64 = all0;
        out[0] = 0.0f;
    }
}

// One CTA per batch. 48 columns (j), 8 lanes per column reducing over i.
// Per step t:
//   raw[j] = log( sum_i exp( r[i] - m + tr[t][i][j] ) ),  m = r[0]
//   r <- raw,  C += m          (true forward value = r + C)
// The per-column max of the reference is replaced by the scalar offset m,
// which keeps exp arguments bounded (values are logsumexps of the same
// distribution; spread is a few units). EPS=1e-12 is negligible since the
// sum always contains a term >= exp(-spread).
__global__ __launch_bounds__(TPB, 1) void crf_main(
    const float* __restrict__ tr,
    const void*  __restrict__ tgt,
    float*       __restrict__ out)
{
    __shared__ float shr[2][NT];
    __shared__ float ts_sh;

    const int tid = threadIdx.x;
    const int b   = blockIdx.x;
    const int j   = tid >> 3;   // column 0..47
    const int sub = tid & 7;    // reduction lane 0..7

    const float* __restrict__ tb = tr + (size_t)b * SEQLEN * NT2;

    if (tid == 0) ts_sh = 0.0f;
    // r_1 = transition[b, 0, START, :]
    if (tid < NT) shr[0][tid] = tb[START_TAG * NT + tid];

    // ---- target path score (gathered) ----
    const int is64 = g_is64;
    float ts = 0.0f;
    for (int s = tid; s < SEQLEN; s += TPB) {
        int cur, prv;
        if (is64) {
            const long long* t64 = (const long long*)tgt + (size_t)b * SEQLEN;
            cur = (int)t64[s];
            prv = (s == 0) ? START_TAG : (int)t64[s - 1];
        } else {
            const int* t32 = (const int*)tgt + b * SEQLEN;
            cur = t32[s];
            prv = (s == 0) ? START_TAG : t32[s - 1];
        }
        ts += tb[(size_t)s * NT2 + prv * NT + cur];
    }
    #pragma unroll
    for (int m = 16; m; m >>= 1) ts += __shfl_xor_sync(0xffffffffu, ts, m);
    if ((tid & 31) == 0) atomicAdd(&ts_sh, ts);

    // ---- forward recurrence with distance-2 register prefetch ----
    const int o0 = sub * NT + j;
    const int o1 = o0 +  8 * NT;
    const int o2 = o0 + 16 * NT;
    const int o3 = o0 + 24 * NT;
    const int o4 = o0 + 32 * NT;
    const int o5 = o0 + 40 * NT;

    float b0[6], b1[6], b2[6];
    {
        const float* p1 = tb + (size_t)1 * NT2;
        b1[0] = p1[o0]; b1[1] = p1[o1]; b1[2] = p1[o2];
        b1[3] = p1[o3]; b1[4] = p1[o4]; b1[5] = p1[o5];
        const float* p2 = tb + (size_t)2 * NT2;
        b2[0] = p2[o0]; b2[1] = p2[o1]; b2[2] = p2[o2];
        b2[3] = p2[o3]; b2[4] = p2[o4]; b2[5] = p2[o5];
    }
    float C = 0.0f;

#define STEP(T, CB, NB)                                                       \
    do {                                                                      \
        if ((T) + 2 < SEQLEN) {                                               \
            const float* pp = tb + (size_t)((T) + 2) * NT2;                   \
            NB[0] = pp[o0]; NB[1] = pp[o1]; NB[2] = pp[o2];                   \
            NB[3] = pp[o3]; NB[4] = pp[o4]; NB[5] = pp[o5];                   \
        }                                                                     \
        __syncthreads();                                                      \
        {                                                                     \
            const float* rin = shr[((T) + 1) & 1];                            \
            float m = rin[0];                                                 \
            C += m;                                                           \
            float e0 = __expf(rin[sub     ] - m + CB[0]);                     \
            float e1 = __expf(rin[sub +  8] - m + CB[1]);                     \
            float e2 = __expf(rin[sub + 16] - m + CB[2]);                     \
            float e3 = __expf(rin[sub + 24] - m + CB[3]);                     \
            float e4 = __expf(rin[sub + 32] - m + CB[4]);                     \
            float e5 = __expf(rin[sub + 40] - m + CB[5]);                     \
            float s = ((e0 + e1) + (e2 + e3)) + (e4 + e5);                    \
            s += __shfl_xor_sync(0xffffffffu, s, 1);                          \
            s += __shfl_xor_sync(0xffffffffu, s, 2);                          \
            s += __shfl_xor_sync(0xffffffffu, s, 4);                          \
            if (sub == 0) shr[(T) & 1][j] = __logf(s);                        \
        }                                                                     \
    } while (0)

    // 511 steps total: 170 x 3 unrolled + 1 tail. Buffer rotation:
    // step t consumes buf[t%3] and prefetches t+2 into buf[(t+2)%3].
    for (int it = 0; it < 170; ++it) {
        int t = 1 + it * 3;
        STEP(t,     b1, b0);
        STEP(t + 1, b2, b1);
        STEP(t + 2, b0, b2);
    }
    STEP(511, b1, b0);
#undef STEP

    __syncthreads();
    if (tid == 0) {
        float F = shr[1][END_TAG] + C;  // true forw[b, END]
        atomicAdd(out, (F - ts_sh) * (1.0f / (float)BSZ));
    }
}

extern "C" void kernel_launch(void* const* d_in, const int* in_sizes, int n_in,
                              void* d_out, int out_size) {
    const void* trans = d_in[0];
    const void* tgt   = d_in[1];
    // Defensive: identify tensors by size (transition is 75.5M elems, target 32K).
    if (n_in >= 2 && in_sizes[0] < in_sizes[1]) {
        trans = d_in[1];
        tgt   = d_in[0];
    }
    crf_prep<<<1, 32>>>((const int*)tgt, (float*)d_out);
    crf_main<<<BSZ, TPB>>>((const float*)trans, tgt, (float*)d_out);
}